// round 1
// baseline (speedup 1.0000x reference)
#include <cuda_runtime.h>

#define N_NODES 100000
#define N_EDGES 1600000
#define F_INP   8
#define H       128
#define NLAYERS 4
#define E_FEAT  16
#define NG      256
#define OUT_F   256

// -------- scratch (device globals; no allocations allowed) --------
__device__ __align__(16) float g_h  [(size_t)N_NODES * H];
__device__ __align__(16) float g_agg[(size_t)N_NODES * H];
__device__ __align__(16) float g_hc [(size_t)N_NODES * H];
__device__ __align__(16) float g_stats[2 * H];
__device__ __align__(16) float g_hp[NG * H];
__device__ __align__(16) float g_cnt[NG];

// -------- node embedding: h = x @ emb_W + emb_b --------
__global__ void k_embed(const float* __restrict__ x,
                        const float* __restrict__ W,
                        const float* __restrict__ b) {
    int i = blockIdx.x;          // node
    int j = threadIdx.x;         // feature 0..127
    const float* xr = x + (size_t)i * F_INP;
    float acc = b[j];
#pragma unroll
    for (int k = 0; k < F_INP; k++)
        acc = fmaf(xr[k], W[k * H + j], acc);
    g_h[(size_t)i * H + j] = acc;
}

// -------- agg = h (scatter target init) + zero BN stat accumulators --------
__global__ void k_copyzero() {
    int idx = blockIdx.x * blockDim.x + threadIdx.x;
    const int total = N_NODES * H / 4;
    if (idx < total)
        ((float4*)g_agg)[idx] = ((const float4*)g_h)[idx];
    if (blockIdx.x == 0 && threadIdx.x < 2 * H)
        g_stats[threadIdx.x] = 0.f;
}

// -------- edge kernel: msg = relu(h[src] + attr@edge_W + edge_b); agg[dst] += msg --------
// One warp per edge; lane owns 4 features. edge_W slice lives in registers.
__global__ void __launch_bounds__(256) k_edge(const int* __restrict__ ei,
                                              const float* __restrict__ attr,
                                              const float* __restrict__ W,
                                              const float* __restrict__ b) {
    const int* src = ei;
    const int* dst = ei + N_EDGES;
    int lane = threadIdx.x & 31;
    int wid  = (blockIdx.x * blockDim.x + threadIdx.x) >> 5;
    int nw   = (gridDim.x * blockDim.x) >> 5;

    float4 w[E_FEAT];
#pragma unroll
    for (int k = 0; k < E_FEAT; k++)
        w[k] = *(const float4*)(W + k * H + lane * 4);
    float4 bb = *(const float4*)(b + lane * 4);

    for (int e = wid; e < N_EDGES; e += nw) {
        int s = src[e], d = dst[e];
        float a = attr[(size_t)e * E_FEAT + (lane & 15)];
        float4 hv = *(const float4*)(g_h + (size_t)s * H + lane * 4);
        float4 acc = bb;
#pragma unroll
        for (int k = 0; k < E_FEAT; k++) {
            float ak = __shfl_sync(0xffffffffu, a, k);
            acc.x = fmaf(ak, w[k].x, acc.x);
            acc.y = fmaf(ak, w[k].y, acc.y);
            acc.z = fmaf(ak, w[k].z, acc.z);
            acc.w = fmaf(ak, w[k].w, acc.w);
        }
        float mx = fmaxf(hv.x + acc.x, 0.f);
        float my = fmaxf(hv.y + acc.y, 0.f);
        float mz = fmaxf(hv.z + acc.z, 0.f);
        float mw = fmaxf(hv.w + acc.w, 0.f);
        float* p = g_agg + (size_t)d * H + lane * 4;
        asm volatile("red.global.add.v4.f32 [%0], {%1,%2,%3,%4};"
                     :: "l"(p), "f"(mx), "f"(my), "f"(mz), "f"(mw) : "memory");
    }
}

// -------- node GEMM: hc = agg @ nn_W + nn_b, with per-feature sum/sumsq for BN --------
// W staged in 64KB dynamic smem; each warp processes 2 nodes at a time (register blocking).
__global__ void __launch_bounds__(256) k_nodegemm(const float* __restrict__ W,
                                                  const float* __restrict__ b) {
    extern __shared__ float sW[];  // H*H floats
    for (int idx = threadIdx.x; idx < H * H / 4; idx += blockDim.x)
        ((float4*)sW)[idx] = ((const float4*)W)[idx];
    __syncthreads();

    int lane = threadIdx.x & 31;
    int wid  = (blockIdx.x * blockDim.x + threadIdx.x) >> 5;
    int nw   = (gridDim.x * blockDim.x) >> 5;
    float4 bb = *(const float4*)(b + lane * 4);

    float4 sum = make_float4(0, 0, 0, 0);
    float4 sq  = make_float4(0, 0, 0, 0);

    for (int i0 = wid * 2; i0 < N_NODES; i0 += nw * 2) {
        const float* a0 = g_agg + (size_t)i0 * H;
        const float* a1 = a0 + H;
        float4 acc0 = bb, acc1 = bb;
#pragma unroll 8
        for (int k4 = 0; k4 < H; k4 += 4) {
            float4 v0 = *(const float4*)(a0 + k4);
            float4 v1 = *(const float4*)(a1 + k4);
            float av0[4] = {v0.x, v0.y, v0.z, v0.w};
            float av1[4] = {v1.x, v1.y, v1.z, v1.w};
#pragma unroll
            for (int kk = 0; kk < 4; kk++) {
                float4 wv = *(const float4*)(sW + (k4 + kk) * H + lane * 4);
                acc0.x = fmaf(av0[kk], wv.x, acc0.x);
                acc0.y = fmaf(av0[kk], wv.y, acc0.y);
                acc0.z = fmaf(av0[kk], wv.z, acc0.z);
                acc0.w = fmaf(av0[kk], wv.w, acc0.w);
                acc1.x = fmaf(av1[kk], wv.x, acc1.x);
                acc1.y = fmaf(av1[kk], wv.y, acc1.y);
                acc1.z = fmaf(av1[kk], wv.z, acc1.z);
                acc1.w = fmaf(av1[kk], wv.w, acc1.w);
            }
        }
        *(float4*)(g_hc + (size_t)i0 * H + lane * 4)       = acc0;
        *(float4*)(g_hc + (size_t)(i0 + 1) * H + lane * 4) = acc1;
        sum.x += acc0.x + acc1.x;  sum.y += acc0.y + acc1.y;
        sum.z += acc0.z + acc1.z;  sum.w += acc0.w + acc1.w;
        sq.x  += acc0.x * acc0.x + acc1.x * acc1.x;
        sq.y  += acc0.y * acc0.y + acc1.y * acc1.y;
        sq.z  += acc0.z * acc0.z + acc1.z * acc1.z;
        sq.w  += acc0.w * acc0.w + acc1.w * acc1.w;
    }
    int f = lane * 4;
    atomicAdd(&g_stats[f + 0], sum.x);
    atomicAdd(&g_stats[f + 1], sum.y);
    atomicAdd(&g_stats[f + 2], sum.z);
    atomicAdd(&g_stats[f + 3], sum.w);
    atomicAdd(&g_stats[H + f + 0], sq.x);
    atomicAdd(&g_stats[H + f + 1], sq.y);
    atomicAdd(&g_stats[H + f + 2], sq.z);
    atomicAdd(&g_stats[H + f + 3], sq.w);
}

// -------- BN stat finalize: stats[j] <- mu, stats[H+j] <- rstd --------
__global__ void k_bnstats() {
    int j = threadIdx.x;
    float s = g_stats[j];
    float q = g_stats[H + j];
    const float inv = 1.0f / (float)N_NODES;
    float mu  = s * inv;
    float var = q * inv - mu * mu;
    g_stats[j]     = mu;
    g_stats[H + j] = rsqrtf(var + 1e-5f);
}

// -------- apply BN + exact GELU + residual: h += gelu(bn(hc)) --------
__global__ void k_apply(const float* __restrict__ gam,
                        const float* __restrict__ bet) {
    int idx = blockIdx.x * blockDim.x + threadIdx.x;
    const int total = N_NODES * H / 4;
    if (idx >= total) return;
    int f = (idx & (H / 4 - 1)) * 4;
    float4 hc  = ((const float4*)g_hc)[idx];
    float4 hv  = ((float4*)g_h)[idx];
    float4 mu4 = *(const float4*)(g_stats + f);
    float4 rs4 = *(const float4*)(g_stats + H + f);
    float4 gg  = *(const float4*)(gam + f);
    float4 bb  = *(const float4*)(bet + f);

    float x0 = (hc.x - mu4.x) * rs4.x * gg.x + bb.x;
    float x1 = (hc.y - mu4.y) * rs4.y * gg.y + bb.y;
    float x2 = (hc.z - mu4.z) * rs4.z * gg.z + bb.z;
    float x3 = (hc.w - mu4.w) * rs4.w * gg.w + bb.w;
    hv.x += x0 * normcdff(x0);
    hv.y += x1 * normcdff(x1);
    hv.z += x2 * normcdff(x2);
    hv.w += x3 * normcdff(x3);
    ((float4*)g_h)[idx] = hv;
}

// -------- zero pooled-h + counts --------
__global__ void k_zerohp() {
    int i = blockIdx.x * blockDim.x + threadIdx.x;
    if (i < NG * H) g_hp[i] = 0.f;
    if (i < NG)     g_cnt[i] = 0.f;
}

// -------- pool h by (sorted) batch: hp[g] = sum_{i in g} h[i]; cnt[g] = |g| --------
__global__ void k_pool(const int* __restrict__ batch) {
    int j = threadIdx.x;  // feature 0..127
    int chunk = (N_NODES + gridDim.x - 1) / gridDim.x;
    int i0 = blockIdx.x * chunk;
    int i1 = min(N_NODES, i0 + chunk);
    if (i0 >= i1) return;
    int curG = batch[i0];
    float acc = 0.f;
    int run = 0;
    for (int i = i0; i < i1; i++) {
        int g = batch[i];
        float v = g_h[(size_t)i * H + j];
        if (g != curG) {
            atomicAdd(&g_hp[curG * H + j], acc);
            if (j == 0) atomicAdd(&g_cnt[curG], (float)run);
            acc = 0.f; run = 0; curG = g;
        }
        acc += v; run++;
    }
    atomicAdd(&g_hp[curG * H + j], acc);
    if (j == 0) atomicAdd(&g_cnt[curG], (float)run);
}

// -------- tiny final GEMM: rep[g] = hp[g] @ lin_W + cnt[g]*lin_b --------
__global__ void k_out(const float* __restrict__ W,
                      const float* __restrict__ b,
                      float* __restrict__ out) {
    int g = blockIdx.x;
    int j = threadIdx.x;  // 0..255
    const float* hp = g_hp + g * H;
    float acc = g_cnt[g] * b[j];
#pragma unroll 8
    for (int k = 0; k < H; k++)
        acc = fmaf(hp[k], W[k * OUT_F + j], acc);
    out[g * OUT_F + j] = acc;
}

extern "C" void kernel_launch(void* const* d_in, const int* in_sizes, int n_in,
                              void* d_out, int out_size) {
    const float* x      = (const float*)d_in[0];
    const int*   ei     = (const int*)  d_in[1];
    const float* attr   = (const float*)d_in[2];
    const int*   batch  = (const int*)  d_in[3];
    const float* emb_W  = (const float*)d_in[4];
    const float* emb_b  = (const float*)d_in[5];
    const float* edge_W = (const float*)d_in[6];
    const float* edge_b = (const float*)d_in[7];
    const float* nn_W   = (const float*)d_in[8];
    const float* nn_b   = (const float*)d_in[9];
    const float* bn_g   = (const float*)d_in[10];
    const float* bn_b   = (const float*)d_in[11];
    const float* lin_W  = (const float*)d_in[12];
    const float* lin_b  = (const float*)d_in[13];
    float* out = (float*)d_out;

    cudaFuncSetAttribute(k_nodegemm,
                         cudaFuncAttributeMaxDynamicSharedMemorySize,
                         H * H * (int)sizeof(float));

    const int ew_grid = 12500;   // N*H/4 / 256

    k_embed<<<N_NODES, H>>>(x, emb_W, emb_b);
    for (int l = 0; l < NLAYERS; l++) {
        k_copyzero<<<ew_grid, 256>>>();
        k_edge<<<8192, 256>>>(ei, attr, edge_W + (size_t)l * E_FEAT * H,
                              edge_b + (size_t)l * H);
        k_nodegemm<<<444, 256, H * H * sizeof(float)>>>(
            nn_W + (size_t)l * H * H, nn_b + (size_t)l * H);
        k_bnstats<<<1, H>>>();
        k_apply<<<ew_grid, 256>>>(bn_g + (size_t)l * H, bn_b + (size_t)l * H);
    }
    k_zerohp<<<128, 256>>>();
    k_pool<<<1024, 128>>>(batch);
    k_out<<<NG, OUT_F>>>(lin_W, lin_b, out);
}

// round 2
// speedup vs baseline: 1.3754x; 1.3754x over previous
#include <cuda_runtime.h>

#define N_NODES 100000
#define N_EDGES 1600000
#define F_INP   8
#define H       128
#define NLAYERS 4
#define E_FEAT  16
#define NG      256
#define OUT_F   256

#define SCAN_CHUNK 512
#define SCAN_NBLK  196   // 196*512 = 100352 >= N_NODES

// ---------------- scratch (device globals; allocations are forbidden) ----------------
__device__ __align__(16) float g_h   [(size_t)N_NODES * H];
__device__ __align__(16) float g_agg [(size_t)N_NODES * H];
__device__ __align__(16) float g_hc  [(size_t)N_NODES * H];
__device__ __align__(16) float g_stats[2 * H];   // raw sum / sumsq accumulators
__device__ __align__(16) float g_bn   [2 * H];   // finalized mu / rstd
__device__ __align__(16) float g_hp  [NG * H];
__device__ float g_cntg[NG];

__device__ int g_cnt_i [N_NODES];
__device__ int g_rowptr[N_NODES + 1];
__device__ int g_cursor[N_NODES];
__device__ int g_bsum  [SCAN_NBLK];
__device__ int g_eix   [N_EDGES];
__device__ int g_srcx  [N_EDGES];
__device__ __align__(16) float g_attrs[(size_t)N_EDGES * E_FEAT];  // attr in CSR order

// ---------------- f32x2 helpers ----------------
typedef unsigned long long u64;
__device__ __forceinline__ u64 pk2(float x, float y) {
    u64 r; asm("mov.b64 %0,{%1,%2};" : "=l"(r) : "f"(x), "f"(y)); return r;
}
__device__ __forceinline__ void up2(u64 p, float& x, float& y) {
    asm("mov.b64 {%0,%1},%2;" : "=f"(x), "=f"(y) : "l"(p));
}
__device__ __forceinline__ u64 fma2(u64 a, u64 b, u64 c) {
    u64 d; asm("fma.rn.f32x2 %0,%1,%2,%3;" : "=l"(d) : "l"(a), "l"(b), "l"(c)); return d;
}

// ================= CSR build (once per call; deterministic) =================
__global__ void k_zero() {
    int i = blockIdx.x * blockDim.x + threadIdx.x;
    if (i < N_NODES) g_cnt_i[i] = 0;
    if (i < 2 * H)   g_stats[i] = 0.f;
    if (i < NG * H)  g_hp[i] = 0.f;
    if (i < NG)      g_cntg[i] = 0.f;
}

__global__ void k_hist(const int* __restrict__ ei) {
    const int* dst = ei + N_EDGES;
    int e = blockIdx.x * blockDim.x + threadIdx.x;
    if (e < N_EDGES) atomicAdd(&g_cnt_i[dst[e]], 1);
}

__global__ void k_scan1() {          // per-chunk sums
    __shared__ int s[256];
    int base = blockIdx.x * SCAN_CHUNK;
    int t = threadIdx.x;
    int v = 0;
    int i0 = base + t, i1 = base + t + 256;
    if (i0 < N_NODES) v += g_cnt_i[i0];
    if (i1 < N_NODES && t + 256 < SCAN_CHUNK) v += g_cnt_i[i1];
    s[t] = v; __syncthreads();
    for (int o = 128; o > 0; o >>= 1) { if (t < o) s[t] += s[t + o]; __syncthreads(); }
    if (t == 0) g_bsum[blockIdx.x] = s[0];
}

__global__ void k_scan2() {          // exclusive scan of block sums (1 block)
    __shared__ int s[SCAN_NBLK];
    int t = threadIdx.x;
    if (t < SCAN_NBLK) s[t] = g_bsum[t];
    __syncthreads();
    if (t == 0) {
        int acc = 0;
        for (int i = 0; i < SCAN_NBLK; i++) { int v = s[i]; s[i] = acc; acc += v; }
    }
    __syncthreads();
    if (t < SCAN_NBLK) g_bsum[t] = s[t];
}

__global__ void k_scan3() {          // intra-chunk exclusive scan -> rowptr, cursor
    __shared__ int s[SCAN_CHUNK];
    int t = threadIdx.x;
    int i = blockIdx.x * SCAN_CHUNK + t;
    int v = (i < N_NODES) ? g_cnt_i[i] : 0;
    s[t] = v; __syncthreads();
    for (int o = 1; o < SCAN_CHUNK; o <<= 1) {
        int tv = (t >= o) ? s[t - o] : 0;
        __syncthreads();
        s[t] += tv;
        __syncthreads();
    }
    int incl = s[t];
    int base = g_bsum[blockIdx.x];
    if (i < N_NODES) {
        int ex = base + incl - v;
        g_rowptr[i] = ex;
        g_cursor[i] = ex;
        if (i == N_NODES - 1) g_rowptr[N_NODES] = base + incl;
    }
}

__global__ void k_fill(const int* __restrict__ ei) {
    const int* dst = ei + N_EDGES;
    int e = blockIdx.x * blockDim.x + threadIdx.x;
    if (e < N_EDGES) {
        int pos = atomicAdd(&g_cursor[dst[e]], 1);
        g_eix[pos] = e;
    }
}

__global__ void k_sortbuckets() {    // insertion sort per bucket -> deterministic order
    int d = blockIdx.x * blockDim.x + threadIdx.x;
    if (d >= N_NODES) return;
    int row = g_rowptr[d], end = g_rowptr[d + 1];
    for (int i = row + 1; i < end; i++) {
        int key = g_eix[i];
        int j = i - 1;
        while (j >= row && g_eix[j] > key) { g_eix[j + 1] = g_eix[j]; j--; }
        g_eix[j + 1] = key;
    }
}

__global__ void k_gbuild(const int* __restrict__ ei, const float* __restrict__ attr) {
    const int* src = ei;
    int pos = blockIdx.x * blockDim.x + threadIdx.x;
    if (pos >= N_EDGES) return;
    int e = g_eix[pos];
    g_srcx[pos] = src[e];
    const float4* ar = (const float4*)(attr + (size_t)e * E_FEAT);
    float4* aw = (float4*)(g_attrs + (size_t)pos * E_FEAT);
    aw[0] = ar[0]; aw[1] = ar[1]; aw[2] = ar[2]; aw[3] = ar[3];
}

// ================= model kernels =================
__global__ void k_embed(const float* __restrict__ x,
                        const float* __restrict__ W,
                        const float* __restrict__ b) {
    int i = blockIdx.x;
    int j = threadIdx.x;
    const float* xr = x + (size_t)i * F_INP;
    float acc = b[j];
#pragma unroll
    for (int k = 0; k < F_INP; k++)
        acc = fmaf(xr[k], W[k * H + j], acc);
    g_h[(size_t)i * H + j] = acc;
}

// agg[d] = h[d] + sum_{e in CSR(d)} relu(h[src_e] + attr_e @ W + b)
// one warp per dst node; edge_W slice in registers as f32x2 pairs.
__global__ void __launch_bounds__(256) k_gatheragg(const float* __restrict__ W,
                                                   const float* __restrict__ b) {
    int lane = threadIdx.x & 31;
    int d = blockIdx.x * 8 + (threadIdx.x >> 5);
    if (d >= N_NODES) return;

    // W columns [lane*4 .. lane*4+3] for all 16 attr feats, packed as f32x2
    u64 w01[E_FEAT], w23[E_FEAT];
#pragma unroll
    for (int k = 0; k < E_FEAT; k++) {
        ulonglong2 wp = *(const ulonglong2*)(W + k * H + lane * 4);
        w01[k] = wp.x; w23[k] = wp.y;
    }
    float4 bb = *(const float4*)(b + lane * 4);
    u64 b01 = pk2(bb.x, bb.y), b23 = pk2(bb.z, bb.w);

    int row = g_rowptr[d], end = g_rowptr[d + 1];
    float4 acc = *(const float4*)(g_h + (size_t)d * H + lane * 4);

    int s = (row < end) ? g_srcx[row] : 0;
    for (int j = row; j < end; j++) {
        int snext = (j + 1 < end) ? g_srcx[j + 1] : 0;
        float a = g_attrs[(size_t)j * E_FEAT + (lane & 15)];
        float4 hs = *(const float4*)(g_h + (size_t)s * H + lane * 4);
        u64 e01 = b01, e23 = b23;
#pragma unroll
        for (int k = 0; k < E_FEAT; k++) {
            float ak = __shfl_sync(0xffffffffu, a, k);
            u64 akk = pk2(ak, ak);
            e01 = fma2(akk, w01[k], e01);
            e23 = fma2(akk, w23[k], e23);
        }
        float e0, e1, e2, e3;
        up2(e01, e0, e1); up2(e23, e2, e3);
        acc.x += fmaxf(hs.x + e0, 0.f);
        acc.y += fmaxf(hs.y + e1, 0.f);
        acc.z += fmaxf(hs.z + e2, 0.f);
        acc.w += fmaxf(hs.w + e3, 0.f);
        s = snext;
    }
    *(float4*)(g_agg + (size_t)d * H + lane * 4) = acc;
}

// hc = agg @ nn_W + nn_b ; per-feature sum/sumsq for BN. 8 nodes per warp, f32x2 FMAs.
__global__ void __launch_bounds__(256) k_nodegemm(const float* __restrict__ W,
                                                  const float* __restrict__ b) {
    extern __shared__ float sW[];   // H*H = 64KB
    for (int idx = threadIdx.x; idx < H * H / 4; idx += blockDim.x)
        ((float4*)sW)[idx] = ((const float4*)W)[idx];
    __syncthreads();

    int lane = threadIdx.x & 31;
    int wid  = (blockIdx.x * blockDim.x + threadIdx.x) >> 5;
    int nw   = (gridDim.x * blockDim.x) >> 5;
    float4 bb = *(const float4*)(b + lane * 4);
    u64 bias01 = pk2(bb.x, bb.y), bias23 = pk2(bb.z, bb.w);

    float4 sum = make_float4(0, 0, 0, 0);
    float4 sq  = make_float4(0, 0, 0, 0);

    for (int i0 = wid * 8; i0 < N_NODES; i0 += nw * 8) {
        u64 acc01[8], acc23[8];
#pragma unroll
        for (int n = 0; n < 8; n++) { acc01[n] = bias01; acc23[n] = bias23; }

#pragma unroll 4
        for (int k4 = 0; k4 < H; k4 += 4) {
            float4 av[8];
#pragma unroll
            for (int n = 0; n < 8; n++)
                av[n] = *(const float4*)(g_agg + (size_t)(i0 + n) * H + k4);
#pragma unroll
            for (int kk = 0; kk < 4; kk++) {
                ulonglong2 wp = *(const ulonglong2*)(sW + (k4 + kk) * H + lane * 4);
#pragma unroll
                for (int n = 0; n < 8; n++) {
                    float a = (kk == 0) ? av[n].x : (kk == 1) ? av[n].y
                             : (kk == 2) ? av[n].z : av[n].w;
                    u64 ap = pk2(a, a);
                    acc01[n] = fma2(ap, wp.x, acc01[n]);
                    acc23[n] = fma2(ap, wp.y, acc23[n]);
                }
            }
        }
#pragma unroll
        for (int n = 0; n < 8; n++) {
            float x0, x1, x2, x3;
            up2(acc01[n], x0, x1); up2(acc23[n], x2, x3);
            *(float4*)(g_hc + (size_t)(i0 + n) * H + lane * 4) =
                make_float4(x0, x1, x2, x3);
            sum.x += x0; sum.y += x1; sum.z += x2; sum.w += x3;
            sq.x += x0 * x0; sq.y += x1 * x1; sq.z += x2 * x2; sq.w += x3 * x3;
        }
    }
    int f = lane * 4;
    atomicAdd(&g_stats[f + 0], sum.x);
    atomicAdd(&g_stats[f + 1], sum.y);
    atomicAdd(&g_stats[f + 2], sum.z);
    atomicAdd(&g_stats[f + 3], sum.w);
    atomicAdd(&g_stats[H + f + 0], sq.x);
    atomicAdd(&g_stats[H + f + 1], sq.y);
    atomicAdd(&g_stats[H + f + 2], sq.z);
    atomicAdd(&g_stats[H + f + 3], sq.w);
}

__global__ void k_bnstats() {        // finalize into g_bn, re-zero g_stats
    int j = threadIdx.x;
    float s = g_stats[j];
    float q = g_stats[H + j];
    const float inv = 1.0f / (float)N_NODES;
    float mu  = s * inv;
    float var = q * inv - mu * mu;
    g_bn[j]     = mu;
    g_bn[H + j] = rsqrtf(var + 1e-5f);
    g_stats[j] = 0.f;
    g_stats[H + j] = 0.f;
}

__global__ void k_apply(const float* __restrict__ gam,
                        const float* __restrict__ bet) {
    int idx = blockIdx.x * blockDim.x + threadIdx.x;
    const int total = N_NODES * H / 4;
    if (idx >= total) return;
    int f = (idx & (H / 4 - 1)) * 4;
    float4 hc  = ((const float4*)g_hc)[idx];
    float4 hv  = ((float4*)g_h)[idx];
    float4 mu4 = *(const float4*)(g_bn + f);
    float4 rs4 = *(const float4*)(g_bn + H + f);
    float4 gg  = *(const float4*)(gam + f);
    float4 bb  = *(const float4*)(bet + f);

    float x0 = (hc.x - mu4.x) * rs4.x * gg.x + bb.x;
    float x1 = (hc.y - mu4.y) * rs4.y * gg.y + bb.y;
    float x2 = (hc.z - mu4.z) * rs4.z * gg.z + bb.z;
    float x3 = (hc.w - mu4.w) * rs4.w * gg.w + bb.w;
    hv.x += x0 * normcdff(x0);
    hv.y += x1 * normcdff(x1);
    hv.z += x2 * normcdff(x2);
    hv.w += x3 * normcdff(x3);
    ((float4*)g_h)[idx] = hv;
}

__global__ void k_pool(const int* __restrict__ batch) {
    int j = threadIdx.x;  // feature 0..127
    int chunk = (N_NODES + gridDim.x - 1) / gridDim.x;
    int i0 = blockIdx.x * chunk;
    int i1 = min(N_NODES, i0 + chunk);
    if (i0 >= i1) return;
    int curG = batch[i0];
    float acc = 0.f;
    int run = 0;
    for (int i = i0; i < i1; i++) {
        int g = batch[i];
        float v = g_h[(size_t)i * H + j];
        if (g != curG) {
            atomicAdd(&g_hp[curG * H + j], acc);
            if (j == 0) atomicAdd(&g_cntg[curG], (float)run);
            acc = 0.f; run = 0; curG = g;
        }
        acc += v; run++;
    }
    atomicAdd(&g_hp[curG * H + j], acc);
    if (j == 0) atomicAdd(&g_cntg[curG], (float)run);
}

__global__ void k_out(const float* __restrict__ W,
                      const float* __restrict__ b,
                      float* __restrict__ out) {
    int g = blockIdx.x;
    int j = threadIdx.x;
    const float* hp = g_hp + g * H;
    float acc = g_cntg[g] * b[j];
#pragma unroll 8
    for (int k = 0; k < H; k++)
        acc = fmaf(hp[k], W[k * OUT_F + j], acc);
    out[g * OUT_F + j] = acc;
}

extern "C" void kernel_launch(void* const* d_in, const int* in_sizes, int n_in,
                              void* d_out, int out_size) {
    const float* x      = (const float*)d_in[0];
    const int*   ei     = (const int*)  d_in[1];
    const float* attr   = (const float*)d_in[2];
    const int*   batch  = (const int*)  d_in[3];
    const float* emb_W  = (const float*)d_in[4];
    const float* emb_b  = (const float*)d_in[5];
    const float* edge_W = (const float*)d_in[6];
    const float* edge_b = (const float*)d_in[7];
    const float* nn_W   = (const float*)d_in[8];
    const float* nn_b   = (const float*)d_in[9];
    const float* bn_g   = (const float*)d_in[10];
    const float* bn_b   = (const float*)d_in[11];
    const float* lin_W  = (const float*)d_in[12];
    const float* lin_b  = (const float*)d_in[13];
    float* out = (float*)d_out;

    cudaFuncSetAttribute(k_nodegemm,
                         cudaFuncAttributeMaxDynamicSharedMemorySize,
                         H * H * (int)sizeof(float));

    const int ew_grid = (N_NODES * H / 4 + 255) / 256;
    const int eg      = (N_EDGES + 255) / 256;

    // ---- CSR build (deterministic) ----
    k_zero<<<(NG * H + 255) / 256 + 400, 256>>>();
    k_hist<<<eg, 256>>>(ei);
    k_scan1<<<SCAN_NBLK, 256>>>();
    k_scan2<<<1, 256>>>();
    k_scan3<<<SCAN_NBLK, SCAN_CHUNK>>>();
    k_fill<<<eg, 256>>>(ei);
    k_sortbuckets<<<(N_NODES + 127) / 128, 128>>>();
    k_gbuild<<<eg, 256>>>(ei, attr);

    // ---- network ----
    k_embed<<<N_NODES, H>>>(x, emb_W, emb_b);
    for (int l = 0; l < NLAYERS; l++) {
        k_gatheragg<<<(N_NODES + 7) / 8, 256>>>(edge_W + (size_t)l * E_FEAT * H,
                                                edge_b + (size_t)l * H);
        k_nodegemm<<<296, 256, H * H * sizeof(float)>>>(
            nn_W + (size_t)l * H * H, nn_b + (size_t)l * H);
        k_bnstats<<<1, H>>>();
        k_apply<<<ew_grid, 256>>>(bn_g + (size_t)l * H, bn_b + (size_t)l * H);
    }
    k_pool<<<1024, 128>>>(batch);
    k_out<<<NG, OUT_F>>>(lin_W, lin_b, out);
}

// round 3
// speedup vs baseline: 1.4281x; 1.0383x over previous
#include <cuda_runtime.h>

#define N_NODES 100000
#define N_EDGES 1600000
#define F_INP   8
#define H       128
#define NLAYERS 4
#define E_FEAT  16
#define NG      256
#define OUT_F   256

#define SCAN_CHUNK 512
#define SCAN_NBLK  196   // 196*512 = 100352 >= N_NODES

// ---------------- scratch (device globals; allocations forbidden) ----------------
__device__ __align__(16) float g_h   [(size_t)N_NODES * H];
__device__ __align__(16) float g_agg [(size_t)N_NODES * H];
__device__ __align__(16) float g_hc  [(size_t)N_NODES * H];
__device__ __align__(16) float g_stats[2 * H];   // sum/sumsq accumulators (self-zeroing)
__device__ __align__(16) float g_bn   [2 * H];   // mu / rstd
__device__ __align__(16) float g_hp  [NG * H];
__device__ float g_cntg[NG];

__device__ int g_cnt_i [N_NODES];      // zero at start (BSS) / re-zeroed by scan3
__device__ int g_rowptr[N_NODES + 1];
__device__ int g_cursor[N_NODES];
__device__ int g_bsum  [SCAN_NBLK];
__device__ int g_eix   [N_EDGES];
__device__ int g_srcx  [N_EDGES];
__device__ __align__(16) float g_attrs[(size_t)N_EDGES * E_FEAT];  // attr in CSR order

// ---------------- f32x2 helpers ----------------
typedef unsigned long long u64;
__device__ __forceinline__ u64 pk2(float x, float y) {
    u64 r; asm("mov.b64 %0,{%1,%2};" : "=l"(r) : "f"(x), "f"(y)); return r;
}
__device__ __forceinline__ void up2(u64 p, float& x, float& y) {
    asm("mov.b64 {%0,%1},%2;" : "=f"(x), "=f"(y) : "l"(p));
}
__device__ __forceinline__ u64 fma2(u64 a, u64 b, u64 c) {
    u64 d; asm("fma.rn.f32x2 %0,%1,%2,%3;" : "=l"(d) : "l"(a), "l"(b), "l"(c)); return d;
}

// ================= launch 0: embed + hist + zero (all independent) =================
// blocks [0, N_NODES): embed node b          (128 threads = H features)
// next 12500 blocks:   histogram of dst      (128 edges each)
// next 257 blocks:     zero g_hp / g_cntg
#define MEGA_EMBED_BLKS  N_NODES
#define MEGA_HIST_BLKS   ((N_EDGES + 127) / 128)
#define MEGA_ZERO_BLKS   ((NG * H + 127) / 128)
__global__ void k_megainit(const float* __restrict__ x,
                           const float* __restrict__ W,
                           const float* __restrict__ b,
                           const int* __restrict__ ei) {
    int blk = blockIdx.x;
    int t = threadIdx.x;
    if (blk < MEGA_EMBED_BLKS) {
        const float* xr = x + (size_t)blk * F_INP;
        float acc = b[t];
#pragma unroll
        for (int k = 0; k < F_INP; k++)
            acc = fmaf(xr[k], W[k * H + t], acc);
        g_h[(size_t)blk * H + t] = acc;
        return;
    }
    blk -= MEGA_EMBED_BLKS;
    if (blk < MEGA_HIST_BLKS) {
        int e = blk * 128 + t;
        if (e < N_EDGES) atomicAdd(&g_cnt_i[ei[N_EDGES + e]], 1);
        return;
    }
    blk -= MEGA_HIST_BLKS;
    int i = blk * 128 + t;
    if (i < NG * H) g_hp[i] = 0.f;
    if (i < NG)     g_cntg[i] = 0.f;
}

// ================= launch 1: per-chunk sums =================
__global__ void k_scan1() {
    __shared__ int s[256];
    int base = blockIdx.x * SCAN_CHUNK;
    int t = threadIdx.x;
    int v = 0;
    int i0 = base + t, i1 = base + t + 256;
    if (i0 < N_NODES) v += g_cnt_i[i0];
    if (i1 < N_NODES) v += g_cnt_i[i1];
    s[t] = v; __syncthreads();
    for (int o = 128; o > 0; o >>= 1) { if (t < o) s[t] += s[t + o]; __syncthreads(); }
    if (t == 0) g_bsum[blockIdx.x] = s[0];
}

// ================= launch 2: intra-chunk scan + inline cross-chunk base =================
// Also re-zeroes g_cnt_i for the next graph replay.
__global__ void k_scan3() {
    __shared__ int s[SCAN_CHUNK];
    __shared__ int sb[256];
    int t = threadIdx.x;
    // base = sum of g_bsum[c], c < blockIdx.x
    int acc = 0;
    if (t < 256) {
        if (t < SCAN_NBLK && t < blockIdx.x) acc = g_bsum[t];
        sb[t] = acc;
    }
    __syncthreads();
    for (int o = 128; o > 0; o >>= 1) { if (t < o) sb[t] += sb[t + o]; __syncthreads(); }
    int base = sb[0];

    int i = blockIdx.x * SCAN_CHUNK + t;
    int v = (i < N_NODES) ? g_cnt_i[i] : 0;
    s[t] = v; __syncthreads();
    for (int o = 1; o < SCAN_CHUNK; o <<= 1) {
        int tv = (t >= o) ? s[t - o] : 0;
        __syncthreads();
        s[t] += tv;
        __syncthreads();
    }
    if (i < N_NODES) {
        int ex = base + s[t] - v;
        g_rowptr[i] = ex;
        g_cursor[i] = ex;
        g_cnt_i[i]  = 0;                      // self-clean for next call
        if (i == N_NODES - 1) g_rowptr[N_NODES] = base + s[t];
    }
}

// ================= launch 3: bucket fill =================
__global__ void k_fill(const int* __restrict__ ei) {
    const int* dst = ei + N_EDGES;
    int e = blockIdx.x * blockDim.x + threadIdx.x;
    if (e < N_EDGES) {
        int pos = atomicAdd(&g_cursor[dst[e]], 1);
        g_eix[pos] = e;
    }
}

// ================= launch 4: per-bucket sort (determinism) + gather src/attr =================
__global__ void k_sortbuild(const int* __restrict__ ei, const float* __restrict__ attr) {
    int d = blockIdx.x * blockDim.x + threadIdx.x;
    if (d >= N_NODES) return;
    int row = g_rowptr[d], end = g_rowptr[d + 1];
    for (int i = row + 1; i < end; i++) {
        int key = g_eix[i];
        int j = i - 1;
        while (j >= row && g_eix[j] > key) { g_eix[j + 1] = g_eix[j]; j--; }
        g_eix[j + 1] = key;
    }
    const int* src = ei;
    for (int p = row; p < end; p++) {
        int e = g_eix[p];
        g_srcx[p] = src[e];
        const float4* ar = (const float4*)(attr + (size_t)e * E_FEAT);
        float4* aw = (float4*)(g_attrs + (size_t)p * E_FEAT);
        float4 a0 = ar[0], a1 = ar[1], a2 = ar[2], a3 = ar[3];
        aw[0] = a0; aw[1] = a1; aw[2] = a2; aw[3] = a3;
    }
}

// ================= gather+aggregate: agg[d] = h[d] + sum relu(h[src]+attr@W+b) =================
// One warp per dst; 2 edges pipelined per iteration; edge_W slice in registers (f32x2).
__global__ void __launch_bounds__(256) k_gatheragg(const float* __restrict__ W,
                                                   const float* __restrict__ b) {
    int lane = threadIdx.x & 31;
    int d = blockIdx.x * 8 + (threadIdx.x >> 5);
    if (d >= N_NODES) return;

    u64 w01[E_FEAT], w23[E_FEAT];
#pragma unroll
    for (int k = 0; k < E_FEAT; k++) {
        ulonglong2 wp = *(const ulonglong2*)(W + k * H + lane * 4);
        w01[k] = wp.x; w23[k] = wp.y;
    }
    float4 bb = *(const float4*)(b + lane * 4);
    u64 b01 = pk2(bb.x, bb.y), b23 = pk2(bb.z, bb.w);

    int row = g_rowptr[d], end = g_rowptr[d + 1];
    float4 acc = *(const float4*)(g_h + (size_t)d * H + lane * 4);

    int j = row;
    for (; j + 2 <= end; j += 2) {
        // issue both gathers + both attr loads before any math
        int s0 = g_srcx[j], s1 = g_srcx[j + 1];
        float4 h0 = *(const float4*)(g_h + (size_t)s0 * H + lane * 4);
        float4 h1 = *(const float4*)(g_h + (size_t)s1 * H + lane * 4);
        float a0 = g_attrs[(size_t)j * E_FEAT + (lane & 15)];
        float a1 = g_attrs[(size_t)(j + 1) * E_FEAT + (lane & 15)];
        u64 p01 = b01, p23 = b23, q01 = b01, q23 = b23;
#pragma unroll
        for (int k = 0; k < E_FEAT; k++) {
            float ak0 = __shfl_sync(0xffffffffu, a0, k);
            float ak1 = __shfl_sync(0xffffffffu, a1, k);
            u64 r0 = pk2(ak0, ak0);
            u64 r1 = pk2(ak1, ak1);
            p01 = fma2(r0, w01[k], p01);
            p23 = fma2(r0, w23[k], p23);
            q01 = fma2(r1, w01[k], q01);
            q23 = fma2(r1, w23[k], q23);
        }
        float e0, e1, e2, e3, f0, f1, f2, f3;
        up2(p01, e0, e1); up2(p23, e2, e3);
        up2(q01, f0, f1); up2(q23, f2, f3);
        acc.x += fmaxf(h0.x + e0, 0.f) + fmaxf(h1.x + f0, 0.f);
        acc.y += fmaxf(h0.y + e1, 0.f) + fmaxf(h1.y + f1, 0.f);
        acc.z += fmaxf(h0.z + e2, 0.f) + fmaxf(h1.z + f2, 0.f);
        acc.w += fmaxf(h0.w + e3, 0.f) + fmaxf(h1.w + f3, 0.f);
    }
    if (j < end) {
        int s0 = g_srcx[j];
        float4 h0 = *(const float4*)(g_h + (size_t)s0 * H + lane * 4);
        float a0 = g_attrs[(size_t)j * E_FEAT + (lane & 15)];
        u64 p01 = b01, p23 = b23;
#pragma unroll
        for (int k = 0; k < E_FEAT; k++) {
            float ak0 = __shfl_sync(0xffffffffu, a0, k);
            u64 r0 = pk2(ak0, ak0);
            p01 = fma2(r0, w01[k], p01);
            p23 = fma2(r0, w23[k], p23);
        }
        float e0, e1, e2, e3;
        up2(p01, e0, e1); up2(p23, e2, e3);
        acc.x += fmaxf(h0.x + e0, 0.f);
        acc.y += fmaxf(h0.y + e1, 0.f);
        acc.z += fmaxf(h0.z + e2, 0.f);
        acc.w += fmaxf(h0.w + e3, 0.f);
    }
    *(float4*)(g_agg + (size_t)d * H + lane * 4) = acc;
}

// ================= node GEMM: hc = agg @ nn_W + nn_b ; BN sum/sumsq =================
__global__ void __launch_bounds__(256) k_nodegemm(const float* __restrict__ W,
                                                  const float* __restrict__ b) {
    extern __shared__ float sW[];   // 64KB
    for (int idx = threadIdx.x; idx < H * H / 4; idx += blockDim.x)
        ((float4*)sW)[idx] = ((const float4*)W)[idx];
    __syncthreads();

    int lane = threadIdx.x & 31;
    int wid  = (blockIdx.x * blockDim.x + threadIdx.x) >> 5;
    int nw   = (gridDim.x * blockDim.x) >> 5;
    float4 bb = *(const float4*)(b + lane * 4);
    u64 bias01 = pk2(bb.x, bb.y), bias23 = pk2(bb.z, bb.w);

    float4 sum = make_float4(0, 0, 0, 0);
    float4 sq  = make_float4(0, 0, 0, 0);

    for (int i0 = wid * 8; i0 < N_NODES; i0 += nw * 8) {
        u64 acc01[8], acc23[8];
#pragma unroll
        for (int n = 0; n < 8; n++) { acc01[n] = bias01; acc23[n] = bias23; }

#pragma unroll 4
        for (int k4 = 0; k4 < H; k4 += 4) {
            float4 av[8];
#pragma unroll
            for (int n = 0; n < 8; n++)
                av[n] = *(const float4*)(g_agg + (size_t)(i0 + n) * H + k4);
#pragma unroll
            for (int kk = 0; kk < 4; kk++) {
                ulonglong2 wp = *(const ulonglong2*)(sW + (k4 + kk) * H + lane * 4);
#pragma unroll
                for (int n = 0; n < 8; n++) {
                    float a = (kk == 0) ? av[n].x : (kk == 1) ? av[n].y
                             : (kk == 2) ? av[n].z : av[n].w;
                    u64 ap = pk2(a, a);
                    acc01[n] = fma2(ap, wp.x, acc01[n]);
                    acc23[n] = fma2(ap, wp.y, acc23[n]);
                }
            }
        }
#pragma unroll
        for (int n = 0; n < 8; n++) {
            float x0, x1, x2, x3;
            up2(acc01[n], x0, x1); up2(acc23[n], x2, x3);
            *(float4*)(g_hc + (size_t)(i0 + n) * H + lane * 4) =
                make_float4(x0, x1, x2, x3);
            sum.x += x0; sum.y += x1; sum.z += x2; sum.w += x3;
            sq.x += x0 * x0; sq.y += x1 * x1; sq.z += x2 * x2; sq.w += x3 * x3;
        }
    }
    int f = lane * 4;
    atomicAdd(&g_stats[f + 0], sum.x);
    atomicAdd(&g_stats[f + 1], sum.y);
    atomicAdd(&g_stats[f + 2], sum.z);
    atomicAdd(&g_stats[f + 3], sum.w);
    atomicAdd(&g_stats[H + f + 0], sq.x);
    atomicAdd(&g_stats[H + f + 1], sq.y);
    atomicAdd(&g_stats[H + f + 2], sq.z);
    atomicAdd(&g_stats[H + f + 3], sq.w);
}

__global__ void k_bnstats() {
    int j = threadIdx.x;
    float s = g_stats[j];
    float q = g_stats[H + j];
    const float inv = 1.0f / (float)N_NODES;
    float mu  = s * inv;
    float var = q * inv - mu * mu;
    g_bn[j]     = mu;
    g_bn[H + j] = rsqrtf(var + 1e-5f);
    g_stats[j] = 0.f;
    g_stats[H + j] = 0.f;
}

__global__ void k_apply(const float* __restrict__ gam,
                        const float* __restrict__ bet) {
    int idx = blockIdx.x * blockDim.x + threadIdx.x;
    const int total = N_NODES * H / 4;
    if (idx >= total) return;
    int f = (idx & (H / 4 - 1)) * 4;
    float4 hc  = ((const float4*)g_hc)[idx];
    float4 hv  = ((float4*)g_h)[idx];
    float4 mu4 = *(const float4*)(g_bn + f);
    float4 rs4 = *(const float4*)(g_bn + H + f);
    float4 gg  = *(const float4*)(gam + f);
    float4 bb  = *(const float4*)(bet + f);

    float x0 = (hc.x - mu4.x) * rs4.x * gg.x + bb.x;
    float x1 = (hc.y - mu4.y) * rs4.y * gg.y + bb.y;
    float x2 = (hc.z - mu4.z) * rs4.z * gg.z + bb.z;
    float x3 = (hc.w - mu4.w) * rs4.w * gg.w + bb.w;
    hv.x += x0 * normcdff(x0);
    hv.y += x1 * normcdff(x1);
    hv.z += x2 * normcdff(x2);
    hv.w += x3 * normcdff(x3);
    ((float4*)g_h)[idx] = hv;
}

__global__ void k_pool(const int* __restrict__ batch) {
    int j = threadIdx.x;
    int chunk = (N_NODES + gridDim.x - 1) / gridDim.x;
    int i0 = blockIdx.x * chunk;
    int i1 = min(N_NODES, i0 + chunk);
    if (i0 >= i1) return;
    int curG = batch[i0];
    float acc = 0.f;
    int run = 0;
    for (int i = i0; i < i1; i++) {
        int g = batch[i];
        float v = g_h[(size_t)i * H + j];
        if (g != curG) {
            atomicAdd(&g_hp[curG * H + j], acc);
            if (j == 0) atomicAdd(&g_cntg[curG], (float)run);
            acc = 0.f; run = 0; curG = g;
        }
        acc += v; run++;
    }
    atomicAdd(&g_hp[curG * H + j], acc);
    if (j == 0) atomicAdd(&g_cntg[curG], (float)run);
}

__global__ void k_out(const float* __restrict__ W,
                      const float* __restrict__ b,
                      float* __restrict__ out) {
    int g = blockIdx.x;
    int j = threadIdx.x;
    const float* hp = g_hp + g * H;
    float acc = g_cntg[g] * b[j];
#pragma unroll 8
    for (int k = 0; k < H; k++)
        acc = fmaf(hp[k], W[k * OUT_F + j], acc);
    out[g * OUT_F + j] = acc;
}

extern "C" void kernel_launch(void* const* d_in, const int* in_sizes, int n_in,
                              void* d_out, int out_size) {
    const float* x      = (const float*)d_in[0];
    const int*   ei     = (const int*)  d_in[1];
    const float* attr   = (const float*)d_in[2];
    const int*   batch  = (const int*)  d_in[3];
    const float* emb_W  = (const float*)d_in[4];
    const float* emb_b  = (const float*)d_in[5];
    const float* edge_W = (const float*)d_in[6];
    const float* edge_b = (const float*)d_in[7];
    const float* nn_W   = (const float*)d_in[8];
    const float* nn_b   = (const float*)d_in[9];
    const float* bn_g   = (const float*)d_in[10];
    const float* bn_b   = (const float*)d_in[11];
    const float* lin_W  = (const float*)d_in[12];
    const float* lin_b  = (const float*)d_in[13];
    float* out = (float*)d_out;

    cudaFuncSetAttribute(k_nodegemm,
                         cudaFuncAttributeMaxDynamicSharedMemorySize,
                         H * H * (int)sizeof(float));

    const int ew_grid = (N_NODES * H / 4 + 255) / 256;
    const int eg      = (N_EDGES + 255) / 256;
    const int mega    = MEGA_EMBED_BLKS + MEGA_HIST_BLKS + MEGA_ZERO_BLKS;

    k_megainit<<<mega, 128>>>(x, emb_W, emb_b, ei);          // launch 0
    k_scan1<<<SCAN_NBLK, 256>>>();                            // 1
    k_scan3<<<SCAN_NBLK, SCAN_CHUNK>>>();                     // 2
    k_fill<<<eg, 256>>>(ei);                                  // 3
    k_sortbuild<<<(N_NODES + 127) / 128, 128>>>(ei, attr);    // 4
    for (int l = 0; l < NLAYERS; l++) {
        k_gatheragg<<<(N_NODES + 7) / 8, 256>>>(              // 5 = layer-0 gather (ncu target)
            edge_W + (size_t)l * E_FEAT * H, edge_b + (size_t)l * H);
        k_nodegemm<<<296, 256, H * H * sizeof(float)>>>(
            nn_W + (size_t)l * H * H, nn_b + (size_t)l * H);
        k_bnstats<<<1, H>>>();
        k_apply<<<ew_grid, 256>>>(bn_g + (size_t)l * H, bn_b + (size_t)l * H);
    }
    k_pool<<<1024, 128>>>(batch);
    k_out<<<NG, OUT_F>>>(lin_W, lin_b, out);
}